// round 3
// baseline (speedup 1.0000x reference)
#include <cuda_runtime.h>
#include <cuda_fp16.h>
#include <cstdint>
#include <math.h>

#define GD 1935      // GATE_DIM
#define OPAD 304     // padded 300 (=19*16)
#define PCOLS 320    // fc3h padded p cols (=5*64)

// ------------------------- device scratch (no allocs) -----------------------
__device__ __align__(16) float g_sg1[GD];
__device__ __align__(16) float g_sg2[GD];
__device__ __align__(16) float g_f[768 * 300];          // gated features @ attr
__device__ __align__(16) float g_U[384 * OPAD];
__device__ __align__(16) float g_V[384 * OPAD];
__device__ __align__(16) float g_P[384 * OPAD];
__device__ __align__(16) float g_Q[384 * OPAD];
__device__ __align__(16) float g_fc1ta[300 * OPAD];     // [d][o] = fc1_w[o][d]
__device__ __align__(16) float g_fc1tb[300 * OPAD];     // [d][o] = fc1_w[o][300+d]
__device__ __align__(16) __half g_fc3h[OPAD * PCOLS];   // [o][p] = fc3_w[p][o]

// ------------------------------- K0: prep ----------------------------------
__global__ void k0_prep(const float* __restrict__ gate1, const float* __restrict__ gate2,
                        const float* __restrict__ fc3w, const float* __restrict__ fc1w,
                        const float* __restrict__ box1, const float* __restrict__ box2,
                        const float* __restrict__ fc2w, const float* __restrict__ fc2b) {
    int i = blockIdx.x * 256 + threadIdx.x;
    if (i < GD) {
        g_sg1[i] = 1.f / (1.f + expf(-gate1[i]));
        g_sg2[i] = 1.f / (1.f + expf(-gate2[i]));
    }
    if (i < OPAD * PCOLS) {               // fc3h[o][p] = fc3_w[p][o]
        int o = i / PCOLS, p = i - o * PCOLS;
        float v = (o < 300 && p < 300) ? fc3w[p * 300 + o] : 0.f;
        g_fc3h[i] = __float2half_rn(v);
    }
    if (i < 300 * OPAD) {                 // fc1t[d][o]
        int d = i / OPAD, o = i - d * OPAD;
        g_fc1ta[i] = (o < 300) ? fc1w[o * 600 + d] : 0.f;
        g_fc1tb[i] = (o < 300) ? fc1w[o * 600 + 300 + d] : 0.f;
    }
    if (i < 384 * OPAD) {                 // spatial P/Q (K=5)
        int n = i / OPAD, o = i - n * OPAD;
        float pv = 0.f, qv = 0.f;
        if (o < 300) {
#pragma unroll
            for (int j = 0; j < 5; j++) {
                pv += box1[n * 5 + j] * fc2w[o * 10 + j];
                qv += box2[n * 5 + j] * fc2w[o * 10 + 5 + j];
            }
            pv += fc2b[o];
        }
        g_P[i] = pv;
        g_Q[i] = qv;
    }
}

// ---- K1: f[768,300] = (feature .* sigmoid(gate)) @ attr[1935,300], fp32 ----
__global__ void k1_feat(const float* __restrict__ f1, const float* __restrict__ f2,
                        const float* __restrict__ attr) {
    __shared__ float As[32 * 34];  // [k][r]
    __shared__ float Bs[32 * 34];  // [k][c]
    int tid = threadIdx.x;
    int tx = tid & 15, ty = tid >> 4;
    int r0 = blockIdx.y * 32, c0 = blockIdx.x * 32;
    float a00 = 0.f, a01 = 0.f, a10 = 0.f, a11 = 0.f;
    for (int kt = 0; kt < 61; ++kt) {
        int k0 = kt * 32;
#pragma unroll
        for (int idx = tid; idx < 1024; idx += 256) {
            // A tile: r = idx>>5 row, k = idx&31 depth
            int r = idx >> 5, k = idx & 31;
            int gk = k0 + k, row = r0 + r;
            float av = 0.f;
            if (gk < GD)
                av = (row < 384) ? f1[row * GD + gk] * g_sg1[gk]
                                 : f2[(row - 384) * GD + gk] * g_sg2[gk];
            As[k * 34 + r] = av;
            // B tile: kb = idx>>5 depth, c = idx&31 col  (independent indices!)
            int kb = idx >> 5, c = idx & 31;
            int gkb = k0 + kb, gc = c0 + c;
            Bs[kb * 34 + c] = (gkb < GD && gc < 300) ? attr[gkb * 300 + gc] : 0.f;
        }
        __syncthreads();
#pragma unroll
        for (int kk = 0; kk < 32; ++kk) {
            float2 a = *(const float2*)&As[kk * 34 + ty * 2];
            float2 b = *(const float2*)&Bs[kk * 34 + tx * 2];
            a00 += a.x * b.x; a01 += a.x * b.y;
            a10 += a.y * b.x; a11 += a.y * b.y;
        }
        __syncthreads();
    }
    int r = r0 + ty * 2, c = c0 + tx * 2;
    if (c < 300) {
        *(float2*)&g_f[r * 300 + c]       = make_float2(a00, a01);
        *(float2*)&g_f[(r + 1) * 300 + c] = make_float2(a10, a11);
    }
}

// --------- K2: U/V[384,304] = f @ fc1t (+fc1_b for U), fp32, K=300 ---------
__global__ void k2_uv(const float* __restrict__ fc1b) {
    __shared__ float As[32 * 34];
    __shared__ float Bs[32 * 34];
    int tid = threadIdx.x;
    int tx = tid & 15, ty = tid >> 4;
    int r0 = blockIdx.y * 32, c0 = blockIdx.x * 32;
    bool isU = (r0 < 384);
    const float* Bmat = isU ? g_fc1ta : g_fc1tb;
    float a00 = 0.f, a01 = 0.f, a10 = 0.f, a11 = 0.f;
    for (int kt = 0; kt < 10; ++kt) {
        int k0 = kt * 32;
#pragma unroll
        for (int idx = tid; idx < 1024; idx += 256) {
            int r = idx >> 5, k = idx & 31;
            int gk = k0 + k;
            As[k * 34 + r] = (gk < 300) ? g_f[(r0 + r) * 300 + gk] : 0.f;
            int kb = idx >> 5, c = idx & 31;     // independent indices for B
            int gkb = k0 + kb, gc = c0 + c;
            Bs[kb * 34 + c] = (gkb < 300 && gc < OPAD) ? Bmat[gkb * OPAD + gc] : 0.f;
        }
        __syncthreads();
#pragma unroll
        for (int kk = 0; kk < 32; ++kk) {
            float2 a = *(const float2*)&As[kk * 34 + ty * 2];
            float2 b = *(const float2*)&Bs[kk * 34 + tx * 2];
            a00 += a.x * b.x; a01 += a.x * b.y;
            a10 += a.y * b.x; a11 += a.y * b.y;
        }
        __syncthreads();
    }
    int r = r0 + ty * 2, c = c0 + tx * 2;
    if (c < OPAD) {
        float b0 = 0.f, b1 = 0.f;
        if (isU) {
            if (c < 300) b0 = fc1b[c];
            if (c + 1 < 300) b1 = fc1b[c + 1];
        }
        float* dst = isU ? g_U : g_V;
        int rr = isU ? r : r - 384;
        *(float2*)&dst[rr * OPAD + c]       = make_float2(a00 + b0, a01 + b1);
        *(float2*)&dst[(rr + 1) * OPAD + c] = make_float2(a10 + b0, a11 + b1);
    }
}

// ------------------------------- K3: fused main -----------------------------
// block: 256 threads (8 warps). pair tile = 8 n x 16 m = 128 pairs.
// warp w owns n = n0 + w (16 m-rows). K = o (304). p in 5 chunks of 64.
constexpr int F_SU = 0;
constexpr int F_SP = F_SU + 8 * OPAD;
constexpr int F_SV = F_SP + 8 * OPAD;
constexpr int F_SQ = F_SV + 16 * OPAD;
constexpr int F_SB = F_SQ + 16 * OPAD;
constexpr int OFF_A = (F_SB + OPAD) * 4;                 // bytes, 59584
constexpr int A_STR = 312;                               // halves per A row
constexpr int OFF_B = OFF_A + 128 * A_STR * 2;           // 139456
constexpr int B_STR = 72;                                // halves per B row
constexpr int SMEM_BYTES = OFF_B + OPAD * B_STR * 2;     // 183232

__device__ __forceinline__ void ldsm_x4(uint32_t a, uint32_t& r0, uint32_t& r1,
                                        uint32_t& r2, uint32_t& r3) {
    asm volatile("ldmatrix.sync.aligned.m8n8.x4.shared.b16 {%0,%1,%2,%3}, [%4];"
                 : "=r"(r0), "=r"(r1), "=r"(r2), "=r"(r3) : "r"(a));
}
__device__ __forceinline__ void ldsm_x4t(uint32_t a, uint32_t& r0, uint32_t& r1,
                                         uint32_t& r2, uint32_t& r3) {
    asm volatile("ldmatrix.sync.aligned.m8n8.x4.trans.shared.b16 {%0,%1,%2,%3}, [%4];"
                 : "=r"(r0), "=r"(r1), "=r"(r2), "=r"(r3) : "r"(a));
}
__device__ __forceinline__ void mma16816(float* c, const uint32_t* a, uint32_t b0, uint32_t b1) {
    asm volatile(
        "mma.sync.aligned.m16n8k16.row.col.f32.f16.f16.f32 "
        "{%0,%1,%2,%3},{%4,%5,%6,%7},{%8,%9},{%0,%1,%2,%3};"
        : "+f"(c[0]), "+f"(c[1]), "+f"(c[2]), "+f"(c[3])
        : "r"(a[0]), "r"(a[1]), "r"(a[2]), "r"(a[3]), "r"(b0), "r"(b1));
}

__global__ __launch_bounds__(256, 1) void k3_main(const float* __restrict__ wloc,
                                                  const float* __restrict__ fc3b,
                                                  float* __restrict__ out) {
    extern __shared__ char smem[];
    float* sf = (float*)smem;
    float* su = sf + F_SU;
    float* sp = sf + F_SP;
    float* sv = sf + F_SV;
    float* sq = sf + F_SQ;
    float* sb = sf + F_SB;
    __half* Asm = (__half*)(smem + OFF_A);
    __half* Bsm = (__half*)(smem + OFF_B);

    int tid = threadIdx.x;
    int lane = tid & 31, w = tid >> 5;
    int n0 = blockIdx.x * 8;
    int m0 = blockIdx.y * 16;

    for (int i = tid; i < 8 * OPAD; i += 256) {
        int r = i / OPAD, o = i - r * OPAD;
        su[i] = g_U[(n0 + r) * OPAD + o];
        sp[i] = g_P[(n0 + r) * OPAD + o];
    }
    for (int i = tid; i < 16 * OPAD; i += 256) {
        int r = i / OPAD, o = i - r * OPAD;
        sv[i] = g_V[(m0 + r) * OPAD + o];
        sq[i] = g_Q[(m0 + r) * OPAD + o];
    }
    for (int i = tid; i < OPAD; i += 256) sb[i] = (i < 300) ? fc3b[i] : 0.f;

    float l0 = wloc[0], l1 = wloc[1];
    float mx = fmaxf(l0, l1);
    float e0 = expf(l0 - mx), e1 = expf(l1 - mx);
    float w0 = e0 / (e0 + e1), w1 = e1 / (e0 + e1);
    __syncthreads();

    // build mixed tile in fp16
    for (int i = tid; i < 128 * OPAD; i += 256) {
        int pr = i / OPAD, o = i - pr * OPAD;
        int ni = pr >> 4, mi = pr & 15;
        float s = su[ni * OPAD + o] + sv[mi * OPAD + o];
        float t = sp[ni * OPAD + o] + sq[mi * OPAD + o];
        Asm[pr * A_STR + o] = __float2half_rn(w0 * fmaxf(s, 0.f) + w1 * fmaxf(t, 0.f));
    }
    __syncthreads();

    uint32_t sbase = (uint32_t)__cvta_generic_to_shared(smem);
    uint32_t aAddr = sbase + OFF_A + ((w * 16 + (lane & 15)) * A_STR + ((lane >> 4) * 8)) * 2;
    uint32_t bAddr = sbase + OFF_B + ((lane & 15) * B_STR + (lane >> 4) * 8) * 2;

    uint32_t a[19][4];
#pragma unroll
    for (int ks = 0; ks < 19; ++ks)
        ldsm_x4(aAddr + ks * 32, a[ks][0], a[ks][1], a[ks][2], a[ks][3]);

    int r1 = lane >> 2, cb = 2 * (lane & 3);
    for (int pc = 0; pc < 5; ++pc) {
        int p0 = pc * 64;
        __syncthreads();  // prior B reads done
        for (int i = tid; i < OPAD * 8; i += 256) {
            int row = i >> 3, q = i & 7;
            *(uint4*)(Bsm + row * B_STR + q * 8) =
                *(const uint4*)(g_fc3h + row * PCOLS + p0 + q * 8);
        }
        __syncthreads();

#pragma unroll
        for (int pj = 0; pj < 4; ++pj) {
            float acc[2][4] = {{0.f, 0.f, 0.f, 0.f}, {0.f, 0.f, 0.f, 0.f}};
#pragma unroll
            for (int ks = 0; ks < 19; ++ks) {
                uint32_t b0, b1, b2, b3;
                ldsm_x4t(bAddr + ks * (16 * B_STR * 2) + pj * 32, b0, b1, b2, b3);
                mma16816(acc[0], a[ks], b0, b1);
                mma16816(acc[1], a[ks], b2, b3);
            }
            int n = n0 + w;
#pragma unroll
            for (int j = 0; j < 2; ++j) {
                int col = p0 + pj * 16 + j * 8 + cb;
                if (col < 300) {
                    size_t base1 = ((size_t)n * 384 + (m0 + r1)) * 300 + col;
                    size_t base2 = ((size_t)n * 384 + (m0 + r1 + 8)) * 300 + col;
                    *(float2*)&out[base1] = make_float2(acc[j][0] + sb[col], acc[j][1] + sb[col + 1]);
                    *(float2*)&out[base2] = make_float2(acc[j][2] + sb[col], acc[j][3] + sb[col + 1]);
                }
            }
        }
    }
}

// ------------------------------- launch -------------------------------------
extern "C" void kernel_launch(void* const* d_in, const int* in_sizes, int n_in,
                              void* d_out, int out_size) {
    const float* feature1 = (const float*)d_in[0];
    const float* box1     = (const float*)d_in[1];
    const float* feature2 = (const float*)d_in[2];
    const float* box2     = (const float*)d_in[3];
    const float* attr     = (const float*)d_in[4];
    const float* gate1    = (const float*)d_in[5];
    const float* gate2    = (const float*)d_in[6];
    const float* wloc     = (const float*)d_in[7];
    const float* fc1_w    = (const float*)d_in[8];
    const float* fc1_b    = (const float*)d_in[9];
    const float* fc2_w    = (const float*)d_in[10];
    const float* fc2_b    = (const float*)d_in[11];
    const float* fc3_w    = (const float*)d_in[12];
    const float* fc3_b    = (const float*)d_in[13];
    float* out = (float*)d_out;

    static bool attr_set = false;
    if (!attr_set) {
        cudaFuncSetAttribute(k3_main, cudaFuncAttributeMaxDynamicSharedMemorySize, SMEM_BYTES);
        attr_set = true;
    }

    k0_prep<<<456, 256>>>(gate1, gate2, fc3_w, fc1_w, box1, box2, fc2_w, fc2_b);
    k1_feat<<<dim3(10, 24), 256>>>(feature1, feature2, attr);
    k2_uv<<<dim3(10, 24), 256>>>(fc1_b);
    k3_main<<<dim3(48, 24), 256, SMEM_BYTES>>>(wloc, fc3_b, out);
}